// round 5
// baseline (speedup 1.0000x reference)
#include <cuda_runtime.h>
#include <cuda_bf16.h>

#define NB 16
#define NP 65536
#define NT 48
#define THRESH 0.35f

// ---------------- scratch (no allocation allowed) ----------------
__device__ float g_bto[NB * NP];                 // best truth overlap per prior
__device__ int   g_bti[NB * NP];                 // best truth idx per prior
__device__ float g_ce[NB * NP];                  // loss_rank (pos -> 0)
__device__ unsigned long long g_bestprior[NB * NT];
__device__ double g_loss_l;
__device__ double g_loss_lm;
__device__ double g_cepos[NB];
__device__ double g_topk[NB];
__device__ int    g_numpos[NB];
__device__ int    g_nposland;

__device__ __forceinline__ float sl1(float d) {
    d = fabsf(d);
    return d < 1.f ? 0.5f * d * d : d - 0.5f;
}

// ---------------- kernel 0: init ----------------
__global__ void init_kernel() {
    int i = threadIdx.x;
    if (i == 0) { g_loss_l = 0.0; g_loss_lm = 0.0; g_nposland = 0; }
    if (i < NB) { g_cepos[i] = 0.0; g_topk[i] = 0.0; g_numpos[i] = 0; }
    for (int j = i; j < NB * NT; j += blockDim.x)
        g_bestprior[j] = 0xFFFFFFFFull;   // pack(iou=0, p=0): first-occurrence default
}

// ---------------- kernel 1: match ----------------
// grid (NP/256, NB), block 256. One thread = one prior.
__global__ void match_kernel(const float4* __restrict__ priors,
                             const float* __restrict__ targets) {
    __shared__ float4 s_box[NT];
    __shared__ float  s_area[NT];
    __shared__ unsigned long long s_best[NT];

    const int n = blockIdx.y;
    const int p = blockIdx.x * 256 + threadIdx.x;

    if (threadIdx.x < NT) {
        const float* tg = targets + (n * NT + threadIdx.x) * 15;
        float4 b = make_float4(tg[0], tg[1], tg[2], tg[3]);
        s_box[threadIdx.x] = b;
        s_area[threadIdx.x] = (b.z - b.x) * (b.w - b.y);
        s_best[threadIdx.x] = 0xFFFFFFFFull;
    }
    __syncthreads();

    float4 pr = priors[p];
    float px1 = pr.x - 0.5f * pr.z, py1 = pr.y - 0.5f * pr.w;
    float px2 = pr.x + 0.5f * pr.z, py2 = pr.y + 0.5f * pr.w;
    float parea = (px2 - px1) * (py2 - py1);

    float bestOv = -1.f;
    int bestT = 0;
    const unsigned long long my_lo = (unsigned long long)(0xFFFFFFFFu - (unsigned)p);

#pragma unroll 4
    for (int t = 0; t < NT; t++) {
        float4 b = s_box[t];
        float ix1 = fmaxf(px1, b.x), iy1 = fmaxf(py1, b.y);
        float ix2 = fminf(px2, b.z), iy2 = fminf(py2, b.w);
        float w = fmaxf(ix2 - ix1, 0.f), h = fmaxf(iy2 - iy1, 0.f);
        float inter = w * h;
        float iou = 0.f;
        if (inter > 0.f)   // skip MUFU divide for non-overlapping pairs
            iou = __fdividef(inter, parea + s_area[t] - inter);
        if (iou > bestOv) { bestOv = iou; bestT = t; }
        if (iou > 0.f) {
            unsigned long long cand =
                ((unsigned long long)__float_as_uint(iou) << 32) | my_lo;
            if (cand > s_best[t]) atomicMax(&s_best[t], cand);
        }
    }

    const int idx = n * NP + p;
    g_bto[idx] = bestOv;   // >= 0 after t=0
    g_bti[idx] = bestT;

    __syncthreads();
    if (threadIdx.x < NT)
        atomicMax(&g_bestprior[n * NT + threadIdx.x], s_best[threadIdx.x]);
}

// ---------------- kernel 2: override (sequential in t, last wins) ----------------
__global__ void override_kernel() {
    int n = threadIdx.x;
    if (n >= NB) return;
    for (int t = 0; t < NT; t++) {
        unsigned long long v = g_bestprior[n * NT + t];
        unsigned p = 0xFFFFFFFFu - (unsigned)(v & 0xFFFFFFFFull);
        g_bto[n * NP + p] = 2.0f;
        g_bti[n * NP + p] = t;
    }
}

// ---------------- kernel 3: per-prior losses + CE ----------------
// grid (NP/256, NB), block 256.
__global__ void loss_kernel(const float4* __restrict__ loc,
                            const float2* __restrict__ conf,
                            const float2* __restrict__ landm,
                            const float4* __restrict__ priors,
                            const float* __restrict__ targets) {
    __shared__ float s_tg[NT * 15];
    const int n = blockIdx.y;
    const int p = blockIdx.x * 256 + threadIdx.x;

    for (int j = threadIdx.x; j < NT * 15; j += 256)
        s_tg[j] = targets[n * NT * 15 + j];
    __syncthreads();

    const int idx = n * NP + p;
    const float bto = g_bto[idx];
    const int bti = g_bti[idx];
    const float* tg = &s_tg[bti * 15];
    const float label = tg[14];
    const float conff = (bto < THRESH) ? 0.f : label;
    const int conft = (int)conff;
    const bool pos = (conft != 0);
    const bool posland = (conft > 0);

    float ll = 0.f, lm = 0.f;
    float4 pr = priors[p];

    if (pos) {
        float cx = (tg[0] + tg[2]) * 0.5f;
        float cy = (tg[1] + tg[3]) * 0.5f;
        float t0 = (cx - pr.x) / (0.1f * pr.z);
        float t1 = (cy - pr.y) / (0.1f * pr.w);
        float t2 = logf((tg[2] - tg[0]) / pr.z) * 5.0f;   // /0.2
        float t3 = logf((tg[3] - tg[1]) / pr.w) * 5.0f;
        float4 ld = loc[idx];
        ll = sl1(ld.x - t0) + sl1(ld.y - t1) + sl1(ld.z - t2) + sl1(ld.w - t3);
    }
    if (posland) {
        const float2* lp = &landm[idx * 5];
        float sx = 0.1f * pr.z, sy = 0.1f * pr.w;
#pragma unroll
        for (int i = 0; i < 5; i++) {
            float2 d = lp[i];
            float gx = (tg[4 + 2 * i] - pr.x) / sx;
            float gy = (tg[5 + 2 * i] - pr.y) / sy;
            lm += sl1(d.x - gx) + sl1(d.y - gy);
        }
    }

    float2 c = conf[idx];
    float m = fmaxf(c.x, c.y);
    float ce = m + __logf(1.f + __expf(-fabsf(c.x - c.y))) - (pos ? c.y : c.x);
    ce = fmaxf(ce, 0.f);
    g_ce[idx] = pos ? 0.f : ce;
    float cep = pos ? ce : 0.f;

    // block reduce
    float a = ll, b = lm, cc = cep;
    int d = pos ? 1 : 0, e = posland ? 1 : 0;
#pragma unroll
    for (int o = 16; o; o >>= 1) {
        a += __shfl_down_sync(0xffffffffu, a, o);
        b += __shfl_down_sync(0xffffffffu, b, o);
        cc += __shfl_down_sync(0xffffffffu, cc, o);
        d += __shfl_down_sync(0xffffffffu, d, o);
        e += __shfl_down_sync(0xffffffffu, e, o);
    }
    __shared__ float r_a[8], r_b[8], r_c[8];
    __shared__ int r_d[8], r_e[8];
    int wid = threadIdx.x >> 5, lane = threadIdx.x & 31;
    if (lane == 0) { r_a[wid] = a; r_b[wid] = b; r_c[wid] = cc; r_d[wid] = d; r_e[wid] = e; }
    __syncthreads();
    if (threadIdx.x == 0) {
        float A = 0, B = 0, C = 0; int D = 0, E = 0;
#pragma unroll
        for (int w = 0; w < 8; w++) { A += r_a[w]; B += r_b[w]; C += r_c[w]; D += r_d[w]; E += r_e[w]; }
        if (A != 0.f) atomicAdd(&g_loss_l, (double)A);
        if (B != 0.f) atomicAdd(&g_loss_lm, (double)B);
        if (C != 0.f) atomicAdd(&g_cepos[n], (double)C);
        if (D) atomicAdd(&g_numpos[n], D);
        if (E) atomicAdd(&g_nposland, E);
    }
}

// ---------------- kernel 4: per-batch top-k sum via radix select ----------------
// <<<NB, 1024>>>
__global__ void topk_kernel() {
    const int n = blockIdx.x;
    const float* ce = &g_ce[n * NP];
    long long k = (long long)7 * (long long)g_numpos[n];
    if (k > NP - 1) k = NP - 1;

    __shared__ unsigned s_hist[256];
    __shared__ unsigned s_prefix, s_mask;
    __shared__ long long s_kk;

    if (k <= 0) { if (threadIdx.x == 0) g_topk[n] = 0.0; return; }
    if (threadIdx.x == 0) { s_prefix = 0u; s_mask = 0u; s_kk = k; }
    __syncthreads();

    for (int pass = 0; pass < 4; pass++) {
        const int shift = 24 - 8 * pass;
        for (int j = threadIdx.x; j < 256; j += blockDim.x) s_hist[j] = 0u;
        __syncthreads();
        const unsigned pf = s_prefix, msk = s_mask;
        for (int j = threadIdx.x; j < NP; j += blockDim.x) {
            unsigned key = __float_as_uint(ce[j]);
            if ((key & msk) == pf) atomicAdd(&s_hist[(key >> shift) & 255u], 1u);
        }
        __syncthreads();
        if (threadIdx.x == 0) {
            long long kk = s_kk, cum = 0;
            int b = 255;
            for (; b >= 0; b--) {
                long long c = (long long)s_hist[b];
                if (cum + c >= kk) break;
                cum += c;
            }
            if (b < 0) b = 0;
            s_prefix = pf | ((unsigned)b << shift);
            s_mask = msk | (0xFFu << shift);
            s_kk = kk - cum;
        }
        __syncthreads();
    }

    const unsigned thr = s_prefix;
    const float thrv = __uint_as_float(thr);
    double sgt = 0.0;
    long long cgt = 0;
    for (int j = threadIdx.x; j < NP; j += blockDim.x) {
        float v = ce[j];
        if (__float_as_uint(v) > thr) { sgt += (double)v; cgt++; }
    }
#pragma unroll
    for (int o = 16; o; o >>= 1) {
        sgt += __shfl_down_sync(0xffffffffu, sgt, o);
        cgt += __shfl_down_sync(0xffffffffu, cgt, o);
    }
    __shared__ double r_s[32];
    __shared__ long long r_c2[32];
    int wid = threadIdx.x >> 5, lane = threadIdx.x & 31;
    if (lane == 0) { r_s[wid] = sgt; r_c2[wid] = cgt; }
    __syncthreads();
    if (threadIdx.x == 0) {
        double S = 0; long long C = 0;
        for (int w = 0; w < 32; w++) { S += r_s[w]; C += r_c2[w]; }
        g_topk[n] = S + (double)(k - C) * (double)thrv;
    }
}

// ---------------- kernel 5: final combine ----------------
__global__ void final_kernel(float* __restrict__ out) {
    if (threadIdx.x == 0) {
        double lc = 0.0;
        long long np = 0;
        for (int n = 0; n < NB; n++) { lc += g_cepos[n] + g_topk[n]; np += g_numpos[n]; }
        double Nn = np < 1 ? 1.0 : (double)np;
        int npl = g_nposland;
        double N1 = npl < 1 ? 1.0 : (double)npl;
        out[0] = (float)(g_loss_l / Nn);
        out[1] = (float)(lc / Nn);
        out[2] = (float)(g_loss_lm / N1);
    }
}

extern "C" void kernel_launch(void* const* d_in, const int* in_sizes, int n_in,
                              void* d_out, int out_size) {
    const float4* loc     = (const float4*)d_in[0];   // (16,65536,4) f32
    const float2* conf    = (const float2*)d_in[1];   // (16,65536,2) f32
    const float2* landm   = (const float2*)d_in[2];   // (16,65536,10) f32
    const float4* priors  = (const float4*)d_in[3];   // (65536,4) f32
    const float*  targets = (const float*)d_in[4];    // (16,48,15) f32
    float* out = (float*)d_out;

    init_kernel<<<1, 256>>>();
    match_kernel<<<dim3(NP / 256, NB), 256>>>(priors, targets);
    override_kernel<<<1, 32>>>();
    loss_kernel<<<dim3(NP / 256, NB), 256>>>(loc, conf, landm, priors, targets);
    topk_kernel<<<NB, 1024>>>();
    final_kernel<<<1, 32>>>(out);
}